// round 6
// baseline (speedup 1.0000x reference)
#include <cuda_runtime.h>
#include <cuda_bf16.h>

#define T_STEPS 2048
#define IN_DIM  118
#define EMB     128
#define H       1536
#define H4      6144
#define H2      1024
#define OUTD    128
#define NBLK    128
#define NTHR    1024   // 16 critical (C) warps + 16 push (P) warps

// ---------------- device-global scratch ----------------------------------------------
// Push matrices, per-block column slices: [blk][1536 chunks][pair p=0..5][row k=0..3]
// word = (blk*1536 + c)*24 + p*4 + k ; element = M[4c+k][12*blk + 2p (+1)] as bf16 pair
__device__ __align__(128) unsigned g_PW1[(size_t)H4 * (H / 2)];   // W_ih1 slices (18.9MB)
__device__ __align__(128) unsigned g_PH0[(size_t)H4 * (H / 2)];   // W_hh0 slices
__device__ __align__(128) unsigned g_PH1[(size_t)H4 * (H / 2)];   // W_hh1 slices
__device__ __align__(128) unsigned g_PWx[(size_t)NBLK * 48 * 128];// per-block x/emb rows
__device__ __align__(128) float g_WCBT[(size_t)H * OUTD];         // (W_out@W_hl)^T
__device__ __align__(128) unsigned g_WMp[EMB * OUTD / 2];         // W_map bf16 pairs
__device__ float g_bcomb[OUTD];
__device__ __align__(16) float g_G0[2][H4];   // gate accumulators, layer 0 (parity)
__device__ __align__(16) float g_G1[2][H4];   // gate accumulators, layer 1
__device__ float g_L[2][OUTD];                // logit accumulators
__device__ unsigned g_count = 0;
__device__ unsigned g_done  = 0;

// ---------------- bf16-pair packing with hi-compensation ------------------------------
__device__ __forceinline__ unsigned pack2(float wlo, float whi) {
    unsigned lo16 = (unsigned)__bfloat16_as_ushort(__float2bfloat16(wlo));
    unsigned base = __float_as_uint(whi) & 0xffff0000u;
    unsigned c0 = base | lo16, c1 = (base + 0x10000u) | lo16, c2 = (base - 0x10000u) | lo16;
    float d0 = fabsf(__uint_as_float(c0) - whi);
    float d1 = fabsf(__uint_as_float(c1) - whi);
    float d2 = fabsf(__uint_as_float(c2) - whi);
    unsigned best = c0; float bd = d0;
    if (d1 < bd) { bd = d1; best = c1; }
    if (d2 < bd) { best = c2; }
    return best;
}

__global__ void pack_all(const float* __restrict__ Wih0, const float* __restrict__ Whh0,
                         const float* __restrict__ Wih1, const float* __restrict__ Whh1,
                         const float* __restrict__ Whl,  const float* __restrict__ Wout,
                         const float* __restrict__ bhl,  const float* __restrict__ bout,
                         const float* __restrict__ Wmap) {
    const size_t nP  = (size_t)H4 * (H / 2);       // words per push matrix
    const size_t nX  = (size_t)NBLK * 48 * 128;
    const size_t nCT = (size_t)H * OUTD;
    const size_t nM  = (size_t)EMB * OUTD / 2;
    const size_t total = 3 * nP + nX + nCT + nM + OUTD + 4 * H4;
    size_t stride = (size_t)gridDim.x * blockDim.x;
    for (size_t i = (size_t)blockIdx.x * blockDim.x + threadIdx.x; i < total; i += stride) {
        if (i < 3 * nP) {
            int m = (int)(i / nP);
            size_t k = i - (size_t)m * nP;
            int b = (int)(k / 36864);              // 1536*24 words per block
            int rem = (int)(k % 36864);
            int c = rem / 24, w = rem % 24;
            int p = w >> 2, kk = w & 3;
            int row = 4 * c + kk;
            int col = 12 * b + 2 * p;
            const float* M = (m == 0) ? Wih1 : (m == 1) ? Whh0 : Whh1;
            unsigned* D = (m == 0) ? g_PW1 : (m == 1) ? g_PH0 : g_PH1;
            D[k] = pack2(M[(size_t)row * H + col], M[(size_t)row * H + col + 1]);
        } else if (i < 3 * nP + nX) {
            size_t k = i - 3 * nP;
            int b = (int)(k / (48 * 128));
            int rem = (int)(k % (48 * 128));
            int idx = rem / 128, pw = rem % 128;
            int g = idx / 12, kk = idx % 12;
            size_t grow = (size_t)g * H + b * 12 + kk;
            int c = 2 * pw;
            float lo = (c < IN_DIM + EMB)     ? Wih0[grow * 246 + c]     : 0.f;
            float hi = (c + 1 < IN_DIM + EMB) ? Wih0[grow * 246 + c + 1] : 0.f;
            g_PWx[k] = pack2(lo, hi);
        } else if (i < 3 * nP + nX + nCT) {
            size_t k = i - 3 * nP - nX;
            int c = (int)(k / OUTD), r = (int)(k % OUTD);
            float s = 0.f;
            #pragma unroll 4
            for (int kk = 0; kk < H2; kk++)
                s = fmaf(__ldg(Wout + r * H2 + kk), __ldg(Whl + (size_t)kk * H + c), s);
            g_WCBT[k] = s;
        } else if (i < 3 * nP + nX + nCT + nM) {
            size_t k = i - 3 * nP - nX - nCT;
            int r = (int)(k / (OUTD / 2)), q = (int)(k % (OUTD / 2));
            g_WMp[k] = pack2(Wmap[r * OUTD + 2 * q], Wmap[r * OUTD + 2 * q + 1]);
        } else if (i < 3 * nP + nX + nCT + nM + OUTD) {
            int r = (int)(i - 3 * nP - nX - nCT - nM);
            float s = 0.f;
            #pragma unroll 4
            for (int kk = 0; kk < H2; kk++) s = fmaf(Wout[r * H2 + kk], bhl[kk], s);
            float bc = s + bout[r];
            g_bcomb[r] = bc;
            g_L[0][r] = bc; g_L[1][r] = bc;
        } else {
            size_t k = i - 3 * nP - nX - nCT - nM - OUTD;   // zero G accumulators
            int buf = (int)(k / H4), r = (int)(k % H4);
            if (buf < 2) g_G0[buf][r] = 0.f; else g_G1[buf - 2][r] = 0.f;
        }
    }
}

// ---------------- core math -----------------------------------------------------------
__device__ __forceinline__ float wred(float a) {
    a += __shfl_xor_sync(0xffffffffu, a, 16);
    a += __shfl_xor_sync(0xffffffffu, a, 8);
    a += __shfl_xor_sync(0xffffffffu, a, 4);
    a += __shfl_xor_sync(0xffffffffu, a, 2);
    a += __shfl_xor_sync(0xffffffffu, a, 1);
    return a;
}
__device__ __forceinline__ float sigmoidf_(float x) { return 1.f / (1.f + expf(-x)); }

__device__ __forceinline__ void bffma2(float& a0, float& a1, unsigned w, float x0, float x1) {
    asm("{\n\t"
        ".reg .b32 lo;\n\t"
        ".reg .b64 wp, xp, ap;\n\t"
        "shl.b32 lo, %2, 16;\n\t"
        "mov.b64 wp, {lo, %2};\n\t"
        "mov.b64 xp, {%3, %4};\n\t"
        "mov.b64 ap, {%0, %1};\n\t"
        "fma.rn.f32x2 ap, wp, xp, ap;\n\t"
        "mov.b64 {%0, %1}, ap;\n\t"
        "}" : "+f"(a0), "+f"(a1) : "r"(w), "f"(x0), "f"(x1));
}

// rank-12 push: this block's 12 h-values into 6144-row accumulator (3 chunks/thread)
__device__ __forceinline__ void push12(const uint4* __restrict__ wbase,
                                       const float* __restrict__ shx,
                                       float* __restrict__ acc, int t5) {
    float x[12];
    #pragma unroll
    for (int i = 0; i < 12; i++) x[i] = shx[i];
    #pragma unroll
    for (int s = 0; s < 3; s++) {
        int c = t5 + s * 512;
        const uint4* q = wbase + (size_t)c * 6;
        uint4 q0 = __ldcg(q), q1 = __ldcg(q + 1), q2 = __ldcg(q + 2);
        uint4 q3 = __ldcg(q + 3), q4 = __ldcg(q + 4), q5 = __ldcg(q + 5);
        float2 r0 = {0, 0}, r1 = {0, 0}, r2 = {0, 0}, r3 = {0, 0};
        bffma2(r0.x, r0.y, q0.x, x[0], x[1]);  bffma2(r1.x, r1.y, q0.y, x[0], x[1]);
        bffma2(r2.x, r2.y, q0.z, x[0], x[1]);  bffma2(r3.x, r3.y, q0.w, x[0], x[1]);
        bffma2(r0.x, r0.y, q1.x, x[2], x[3]);  bffma2(r1.x, r1.y, q1.y, x[2], x[3]);
        bffma2(r2.x, r2.y, q1.z, x[2], x[3]);  bffma2(r3.x, r3.y, q1.w, x[2], x[3]);
        bffma2(r0.x, r0.y, q2.x, x[4], x[5]);  bffma2(r1.x, r1.y, q2.y, x[4], x[5]);
        bffma2(r2.x, r2.y, q2.z, x[4], x[5]);  bffma2(r3.x, r3.y, q2.w, x[4], x[5]);
        bffma2(r0.x, r0.y, q3.x, x[6], x[7]);  bffma2(r1.x, r1.y, q3.y, x[6], x[7]);
        bffma2(r2.x, r2.y, q3.z, x[6], x[7]);  bffma2(r3.x, r3.y, q3.w, x[6], x[7]);
        bffma2(r0.x, r0.y, q4.x, x[8], x[9]);  bffma2(r1.x, r1.y, q4.y, x[8], x[9]);
        bffma2(r2.x, r2.y, q4.z, x[8], x[9]);  bffma2(r3.x, r3.y, q4.w, x[8], x[9]);
        bffma2(r0.x, r0.y, q5.x, x[10], x[11]); bffma2(r1.x, r1.y, q5.y, x[10], x[11]);
        bffma2(r2.x, r2.y, q5.z, x[10], x[11]); bffma2(r3.x, r3.y, q5.w, x[10], x[11]);
        float v0 = r0.x + r0.y, v1 = r1.x + r1.y, v2 = r2.x + r2.y, v3 = r3.x + r3.y;
        asm volatile("red.relaxed.gpu.global.add.v4.f32 [%0], {%1, %2, %3, %4};"
                     :: "l"(acc + 4 * c), "f"(v0), "f"(v1), "f"(v2), "f"(v3) : "memory");
    }
}

// local x/emb row-dot: 3 rows/warp over 256 cols (L1-resident weights)
__device__ __forceinline__ void dotx3(const unsigned* __restrict__ w0,
                                      const unsigned* __restrict__ w1,
                                      const unsigned* __restrict__ w2,
                                      const float* __restrict__ sx, int lane,
                                      float& s0, float& s1, float& s2) {
    int kf = lane * 8, kw = lane * 4;
    float4 x0 = *reinterpret_cast<const float4*>(sx + kf);
    float4 x1 = *reinterpret_cast<const float4*>(sx + kf + 4);
    uint4 v0 = __ldg(reinterpret_cast<const uint4*>(w0 + kw));
    uint4 v1 = __ldg(reinterpret_cast<const uint4*>(w1 + kw));
    uint4 v2 = __ldg(reinterpret_cast<const uint4*>(w2 + kw));
    float2 a0 = {0, 0}, a1 = {0, 0}, a2 = {0, 0};
    bffma2(a0.x, a0.y, v0.x, x0.x, x0.y); bffma2(a0.x, a0.y, v0.y, x0.z, x0.w);
    bffma2(a0.x, a0.y, v0.z, x1.x, x1.y); bffma2(a0.x, a0.y, v0.w, x1.z, x1.w);
    bffma2(a1.x, a1.y, v1.x, x0.x, x0.y); bffma2(a1.x, a1.y, v1.y, x0.z, x0.w);
    bffma2(a1.x, a1.y, v1.z, x1.x, x1.y); bffma2(a1.x, a1.y, v1.w, x1.z, x1.w);
    bffma2(a2.x, a2.y, v2.x, x0.x, x0.y); bffma2(a2.x, a2.y, v2.y, x0.z, x0.w);
    bffma2(a2.x, a2.y, v2.z, x1.x, x1.y); bffma2(a2.x, a2.y, v2.w, x1.z, x1.w);
    s0 = wred(a0.x + a0.y); s1 = wred(a1.x + a1.y); s2 = wred(a2.x + a2.y);
}

#define BARC() asm volatile("bar.sync 1, 512;" ::: "memory")

__device__ __forceinline__ void bar_arrive_leader() {
    asm volatile("red.release.gpu.global.add.u32 [%0], 1;" :: "l"(&g_count) : "memory");
}
__device__ __forceinline__ void bar_poll_leader(unsigned target) {
    unsigned v;
    do {
        asm volatile("ld.acquire.gpu.global.u32 %0, [%1];" : "=r"(v) : "l"(&g_count) : "memory");
    } while (v < target);
}

// ---------------- persistent main kernel ----------------------------------------------
__global__ void __launch_bounds__(NTHR, 1) lstm_main(
    const float* __restrict__ inputVecs,
    const float* __restrict__ h0in, const float* __restrict__ c0in,
    const float* __restrict__ bi0, const float* __restrict__ bh0,
    const float* __restrict__ bi1, const float* __restrict__ bh1,
    const float* __restrict__ bm,
    float* __restrict__ out) {
    __shared__ __align__(16) float sxx[256];
    __shared__ __align__(16) float sh0[12], sh1[12];
    __shared__ float sg0[48], sg1[48], sgate[48];
    __shared__ float bA[48], bB[48];
    __shared__ float sy[OUTD], semb[EMB], sbm[EMB];

    const int tid = threadIdx.x, lane = tid & 31, bid = blockIdx.x;
    const bool isC = tid < 512;
    const int t5 = isC ? tid : tid - 512;     // 0..511 within group

    // push-slice bases for this block
    const uint4* PW1 = reinterpret_cast<const uint4*>(g_PW1) + (size_t)bid * 1536 * 6;
    const uint4* PH0 = reinterpret_cast<const uint4*>(g_PH0) + (size_t)bid * 1536 * 6;
    const uint4* PH1 = reinterpret_cast<const uint4*>(g_PH1) + (size_t)bid * 1536 * 6;

    // C-side per-thread constants
    const int wid = tid >> 5;                 // 0..15 for C
    const int i0 = wid * 3;
    int grow = 0;
    if (tid < 48) grow = (tid / 12) * H + bid * 12 + (tid % 12);

    float cA = 0.f, cB = 0.f;
    if (isC && wid == 0 && lane < 12) {
        int j = bid * 12 + lane;
        cA = c0in[j]; cB = c0in[H + j];
        sh0[lane] = h0in[j];          // initial h for prologue pushes
        sh1[lane] = h0in[H + j];
    }
    if (tid < 48) {
        bA[tid] = bi0[grow] + bh0[grow];
        bB[tid] = bi1[grow] + bh1[grow];
    }
    if (isC) for (int i = t5; i < EMB; i += 512) { semb[i] = 0.f; sbm[i] = __ldg(bm + i); }
    __syncthreads();

    // prologue: P pushes initial-state hh contributions into buffers 0
    if (!isC) {
        push12(PH0, sh0, &g_G0[0][0], t5);
        push12(PH1, sh1, &g_G1[0][0], t5);
    }
    __syncthreads();
    unsigned ep = NBLK;
    if (tid == 0) { bar_arrive_leader(); bar_poll_leader(ep); }

    for (int t = 0; t < T_STEPS; ++t) {
        const int par = t & 1;
        __syncthreads();                                   // sync0: P Whh1(t-1) done; semb ready
        if (isC) {
            if (tid < 48) { sg0[tid] = __ldcg(&g_G0[par][grow]); g_G0[par][grow] = 0.f; }
            if (tid < 256) {
                float v = 0.f;
                if (tid < IN_DIM)            v = __ldg(inputVecs + (size_t)t * IN_DIM + tid);
                else if (tid < IN_DIM + EMB) v = semb[tid - IN_DIM];
                sxx[tid] = v;
            }
        }
        __syncthreads();                                   // sync1: sxx, sg0 ready
        if (isC) {
            const unsigned* w0 = g_PWx + ((size_t)bid * 48 + i0) * 128;
            float s0, s1, s2;
            dotx3(w0, w0 + 128, w0 + 256, sxx, lane, s0, s1, s2);
            if (lane == 0) {
                sgate[i0]     = s0 + sg0[i0]     + bA[i0];
                sgate[i0 + 1] = s1 + sg0[i0 + 1] + bA[i0 + 1];
                sgate[i0 + 2] = s2 + sg0[i0 + 2] + bA[i0 + 2];
            }
        }
        __syncthreads();                                   // sync2: sgate ready
        if (isC && wid == 0 && lane < 12) {
            float gi = sigmoidf_(sgate[lane]);
            float gf = sigmoidf_(sgate[12 + lane]);
            float gg = tanhf    (sgate[24 + lane]);
            float go = sigmoidf_(sgate[36 + lane]);
            cA = gf * cA + gi * gg;
            sh0[lane] = go * tanhf(cA);
        }
        __syncthreads();                                   // sync3: h0n ready
        if (isC) {
            push12(PW1, sh0, &g_G1[par][0], t5);           // critical: ih1 contribution
            BARC();
            if (tid == 0) { ep += NBLK; bar_arrive_leader(); bar_poll_leader(ep); }  // bar1
        } else {
            push12(PH0, sh0, &g_G0[par ^ 1][0], t5);       // prefetch: layer0 hh for t+1
        }
        __syncthreads();                                   // sync4: G1 complete; P hh0 done
        if (isC) {
            if (tid < 48) { sg1[tid] = __ldcg(&g_G1[par][grow]); g_G1[par][grow] = 0.f; }
            BARC();
            if (wid == 0 && lane < 12) {
                float gi = sigmoidf_(sg1[lane]      + bB[lane]);
                float gf = sigmoidf_(sg1[12 + lane] + bB[12 + lane]);
                float gg = tanhf    (sg1[24 + lane] + bB[24 + lane]);
                float go = sigmoidf_(sg1[36 + lane] + bB[36 + lane]);
                cB = gf * cB + gi * gg;
                sh1[lane] = go * tanhf(cB);
            }
        }
        __syncthreads();                                   // sync6: h1n ready
        if (isC) {
            if (tid < OUTD) {                              // logit rank-12 push
                const float* wc = g_WCBT + (size_t)(bid * 12) * OUTD + tid;
                float p = 0.f;
                #pragma unroll
                for (int i = 0; i < 12; i++) p = fmaf(__ldg(wc + i * OUTD), sh1[i], p);
                asm volatile("red.relaxed.gpu.global.add.f32 [%0], %1;"
                             :: "l"(&g_L[par][tid]), "f"(p) : "memory");
            }
            BARC();
            if (tid == 0) { ep += NBLK; bar_arrive_leader(); bar_poll_leader(ep); }  // bar2
            BARC();
            if (tid < OUTD) sy[tid] = __ldcg(&g_L[par][tid]);
            if (tid == 48) g_L[par ^ 1][bid] = __ldg(&g_bcomb[bid]);  // reset for t+2
            BARC();
            if (wid == 0) {
                float v0 = sy[lane], v1 = sy[lane + 32], v2 = sy[lane + 64], v3 = sy[lane + 96];
                float m = fmaxf(fmaxf(v0, v1), fmaxf(v2, v3));
                #pragma unroll
                for (int o = 16; o; o >>= 1) m = fmaxf(m, __shfl_xor_sync(0xffffffffu, m, o));
                float e0 = expf(v0 - m), e1 = expf(v1 - m), e2 = expf(v2 - m), e3 = expf(v3 - m);
                float s = wred(e0 + e1 + e2 + e3);
                float inv = 1.f / s;
                e0 *= inv; e1 *= inv; e2 *= inv; e3 *= inv;
                sy[lane] = e0; sy[lane + 32] = e1; sy[lane + 64] = e2; sy[lane + 96] = e3;
                if (bid == 0) {
                    float* op = out + (size_t)t * OUTD;
                    op[lane] = e0; op[lane + 32] = e1; op[lane + 64] = e2; op[lane + 96] = e3;
                }
            }
            BARC();
            {   // emb = Wmap @ y + bm (L1-resident pairs)
                float xa = sy[lane * 4], xb = sy[lane * 4 + 1];
                float xc = sy[lane * 4 + 2], xd = sy[lane * 4 + 3];
                #pragma unroll
                for (int q = 0; q < 8; q++) {
                    int r = wid * 8 + q;
                    const unsigned* wm = g_WMp + r * (OUTD / 2) + lane * 2;
                    float a0 = 0.f, a1 = 0.f;
                    bffma2(a0, a1, __ldg(wm), xa, xb);
                    bffma2(a0, a1, __ldg(wm + 1), xc, xd);
                    float s = wred(a0 + a1);
                    if (lane == 0) semb[r] = s + sbm[r];
                }
            }
        } else {
            push12(PH1, sh1, &g_G1[par ^ 1][0], t5);       // prefetch: layer1 hh for t+1
        }
    }

    // end-of-launch reset of barrier counters (last arriver), for graph replay
    __syncthreads();
    if (tid == 0) {
        __threadfence();
        if (atomicAdd(&g_done, 1u) == NBLK - 1) {
            g_count = 0u;
            g_done = 0u;
            __threadfence();
        }
    }
}

// ---------------- launch --------------------------------------------------------------
extern "C" void kernel_launch(void* const* d_in, const int* in_sizes, int n_in,
                              void* d_out, int out_size) {
    const float* inputVecs = (const float*)d_in[0];
    const float* h0    = (const float*)d_in[1];
    const float* c0    = (const float*)d_in[2];
    const float* W_ih0 = (const float*)d_in[3];
    const float* W_hh0 = (const float*)d_in[4];
    const float* b_ih0 = (const float*)d_in[5];
    const float* b_hh0 = (const float*)d_in[6];
    const float* W_ih1 = (const float*)d_in[7];
    const float* W_hh1 = (const float*)d_in[8];
    const float* b_ih1 = (const float*)d_in[9];
    const float* b_hh1 = (const float*)d_in[10];
    const float* W_hl  = (const float*)d_in[11];
    const float* b_hl  = (const float*)d_in[12];
    const float* W_out = (const float*)d_in[13];
    const float* b_out = (const float*)d_in[14];
    const float* W_map = (const float*)d_in[15];
    const float* b_map = (const float*)d_in[16];

    pack_all<<<2048, 256>>>(W_ih0, W_hh0, W_ih1, W_hh1, W_hl, W_out, b_hl, b_out, W_map);
    lstm_main<<<NBLK, NTHR>>>(inputVecs, h0, c0,
                              b_ih0, b_hh0, b_ih1, b_hh1,
                              b_map, (float*)d_out);
}